// round 14
// baseline (speedup 1.0000x reference)
#include <cuda_runtime.h>
#include <cuda_fp16.h>
#include <cstdint>
#include <cstddef>

#define Bsz   4
#define Tsz   2048
#define Csz   1024
#define Hn    16
#define Mrows (Bsz * Tsz)   // 8192

// 0.125 * log2(e): folded into q so softmax runs in exp2 domain
#define QSCALE 0.18033688011112042f

// Scratch (fp16 operands everywhere; f32 accumulation in-kernel)
__device__ __half g_qkvh [(size_t)Mrows * 3 * Csz];  // [8192, 3072]
__device__ __half g_yh   [(size_t)Mrows * Csz];      // [8192, 1024]
__device__ __half g_xh   [(size_t)Mrows * Csz];      // x in fp16
__device__ __half g_wqkvh[(size_t)Csz * 3 * Csz];    // [1024, 3072] natural
__device__ __half g_wph  [(size_t)Csz * Csz];        // [1024, 1024] natural

// ---------------------------------------------------------------------------
// Helpers (non-'a' PTX: cp.async + mma.sync + ldmatrix, sm_80 baseline)
// ---------------------------------------------------------------------------
__device__ __forceinline__ uint32_t smem_to_u32(const void* p) {
    uint32_t a;
    asm("{ .reg .u64 t; cvta.to.shared.u64 t, %1; cvt.u32.u64 %0, t; }"
        : "=r"(a) : "l"(p));
    return a;
}
__device__ __forceinline__ float ex2(float x) {
    float r;
    asm("ex2.approx.f32 %0, %1;" : "=f"(r) : "f"(x));
    return r;
}
__device__ __forceinline__ uint32_t ex2h2(uint32_t x) {
    uint32_t r;
    asm("ex2.approx.f16x2 %0, %1;" : "=r"(r) : "r"(x));
    return r;
}
__device__ __forceinline__ uint32_t packh2(float lo, float hi) {
    __half2 h = __floats2half2_rn(lo, hi);
    return *reinterpret_cast<uint32_t*>(&h);
}
__device__ __forceinline__ float2 h2f2(uint32_t p) {
    return __half22float2(*reinterpret_cast<__half2*>(&p));
}
__device__ __forceinline__ void ldsm4(uint32_t addr, uint32_t* r) {
    asm volatile("ldmatrix.sync.aligned.m8n8.x4.shared.b16 {%0,%1,%2,%3}, [%4];"
        : "=r"(r[0]), "=r"(r[1]), "=r"(r[2]), "=r"(r[3]) : "r"(addr));
}
__device__ __forceinline__ void ldsm4t(uint32_t addr, uint32_t* r) {
    asm volatile("ldmatrix.sync.aligned.m8n8.x4.trans.shared.b16 {%0,%1,%2,%3}, [%4];"
        : "=r"(r[0]), "=r"(r[1]), "=r"(r[2]), "=r"(r[3]) : "r"(addr));
}

#define CP_ASYNC16(dst, src) \
    asm volatile("cp.async.cg.shared.global [%0], [%1], 16;" :: "r"(dst), "l"(src) : "memory")
#define CP_COMMIT() asm volatile("cp.async.commit_group;" ::: "memory")
#define CP_WAIT(n)  asm volatile("cp.async.wait_group %0;" :: "n"(n) : "memory")

// D += A*B, m16n8k16 fp16 inputs, f32 accumulate (A row-major, B col-major)
#define MMA_F16(d, a, b) \
    asm volatile("mma.sync.aligned.m16n8k16.row.col.f32.f16.f16.f32 " \
        "{%0,%1,%2,%3}, {%4,%5,%6,%7}, {%8,%9}, {%0,%1,%2,%3};" \
        : "+f"((d)[0]), "+f"((d)[1]), "+f"((d)[2]), "+f"((d)[3]) \
        : "r"((a)[0]), "r"((a)[1]), "r"((a)[2]), "r"((a)[3]), \
          "r"((b)[0]), "r"((b)[1]))

// ---------------------------------------------------------------------------
// fp16 GEMM: C[M,N] = A[M,1024] @ W[1024,N] + bias   (W NATURAL layout)
// 128x128 CTA tile, BK=64, 3-stage cp.async, 128 threads (2x2 warps,
// warp tile 64x64). W tile [64k][128n] rows 256B via ldsm4t.
// qkvMode=1: fp16 out to g_qkvh (q pre-scaled).
// ---------------------------------------------------------------------------
#define KCH 16
#define STAGE_B 32768
#define GEMM_SMEM (3 * STAGE_B)

__global__ __launch_bounds__(128, 2) void gemm_h_kernel(
    const __half* __restrict__ A,
    const __half* __restrict__ W,
    const float* __restrict__ bias,
    float* __restrict__ Cf,
    int Ntot,
    int qkvMode)
{
    extern __shared__ char smraw[];
    uint32_t smemB = smem_to_u32(smraw);

    int tid = threadIdx.x, lane = tid & 31, warp = tid >> 5;
    int wm = warp >> 1, wn = warp & 1;
    int tg = lane >> 2, ti = lane & 3;
    int t_ = lane >> 3, rr = lane & 7;
    int row0 = blockIdx.y * 128, col0 = blockIdx.x * 128;

    int ldrA  = tid >> 3;
    int lsegA = tid & 7;
    uint32_t lswA = ((uint32_t)(lsegA ^ (ldrA & 7))) << 4;
    const __half* gA = A + (size_t)(row0 + ldrA) * 1024 + lsegA * 8;

    int ldrW  = tid >> 4;
    int lsegW = tid & 15;
    uint32_t lswW = ((uint32_t)(lsegW ^ ldrW)) << 4;
    const __half* gW = W + (size_t)ldrW * Ntot + col0 + lsegW * 8;

    uint32_t arow[4];
    #pragma unroll
    for (int i = 0; i < 4; i++)
        arow[i] = (uint32_t)((wm * 64 + i * 16 + (t_ & 1) * 8 + rr) * 128);

    float acc[4][8][4];
    #pragma unroll
    for (int i = 0; i < 4; i++)
        #pragma unroll
        for (int j = 0; j < 8; j++)
            #pragma unroll
            for (int q = 0; q < 4; q++) acc[i][j][q] = 0.f;

    auto load_stage = [&](int c) {
        if (c < KCH) {
            uint32_t base = smemB + (uint32_t)(c % 3) * STAGE_B;
            #pragma unroll
            for (int j = 0; j < 8; j++) {
                CP_ASYNC16(base + (uint32_t)((ldrA + 16 * j) * 128) + lswA,
                           gA + c * 64 + (size_t)j * 16 * 1024);
                CP_ASYNC16(base + 16384 + (uint32_t)((ldrW + 8 * j) * 256) + lswW,
                           gW + (size_t)(c * 64 + 8 * j) * Ntot);
            }
        }
        CP_COMMIT();
    };

    load_stage(0);
    load_stage(1);

    #pragma unroll 1
    for (int c = 0; c < KCH; ++c) {
        CP_WAIT(1);
        __syncthreads();
        load_stage(c + 2);

        uint32_t AsB = smemB + (uint32_t)(c % 3) * STAGE_B;
        uint32_t BsB = AsB + 16384;

        #pragma unroll
        for (int ks = 0; ks < 4; ks++) {
            uint32_t af[4][4], bf[4][4];
            #pragma unroll
            for (int i = 0; i < 4; i++)
                ldsm4(AsB + arow[i] + ((uint32_t)((ks * 2 + (t_ >> 1)) ^ rr) << 4), af[i]);
            #pragma unroll
            for (int p = 0; p < 4; p++)
                ldsm4t(BsB + (uint32_t)((ks * 16 + (t_ & 1) * 8 + rr) * 256)
                           + ((uint32_t)((wn * 8 + p * 2 + (t_ >> 1)) ^ rr) << 4), bf[p]);
            #pragma unroll
            for (int i = 0; i < 4; i++)
                #pragma unroll
                for (int p = 0; p < 4; p++) {
                    MMA_F16(acc[i][2 * p],     af[i], &bf[p][0]);
                    MMA_F16(acc[i][2 * p + 1], af[i], &bf[p][2]);
                }
        }
    }

    if (qkvMode) {
        float osc = (col0 < 1024) ? QSCALE : 1.0f;
        #pragma unroll
        for (int i = 0; i < 4; i++) {
            int m = row0 + wm * 64 + i * 16 + tg;
            #pragma unroll
            for (int j = 0; j < 8; j++) {
                int n = col0 + wn * 64 + j * 8 + 2 * ti;
                float bx = __ldg(bias + n), by = __ldg(bias + n + 1);
                uint32_t h0 = packh2((acc[i][j][0] + bx) * osc, (acc[i][j][1] + by) * osc);
                uint32_t h1 = packh2((acc[i][j][2] + bx) * osc, (acc[i][j][3] + by) * osc);
                *(uint32_t*)&g_qkvh[(size_t)m * 3072 + n] = h0;
                *(uint32_t*)&g_qkvh[(size_t)(m + 8) * 3072 + n] = h1;
            }
        }
    } else {
        #pragma unroll
        for (int i = 0; i < 4; i++) {
            int m = row0 + wm * 64 + i * 16 + tg;
            #pragma unroll
            for (int j = 0; j < 8; j++) {
                int n = col0 + wn * 64 + j * 8 + 2 * ti;
                float bx = __ldg(bias + n), by = __ldg(bias + n + 1);
                *(float2*)&Cf[(size_t)m * Ntot + n] =
                    make_float2(acc[i][j][0] + bx, acc[i][j][1] + by);
                *(float2*)&Cf[(size_t)(m + 8) * Ntot + n] =
                    make_float2(acc[i][j][2] + bx, acc[i][j][3] + by);
            }
        }
    }
}

// ---------------------------------------------------------------------------
// Fused prep: f32 -> fp16 for x, w_qkv, w_proj in ONE launch (no transposes).
// ---------------------------------------------------------------------------
#define X_F4   (Mrows * Csz / 4)
#define WQ_F4  (Csz * 3 * Csz / 4)
#define WP_F4  (Csz * Csz / 4)
#define ALL_F4 (X_F4 + WQ_F4 + WP_F4)

__global__ __launch_bounds__(256) void prep_kernel(
    const float4* __restrict__ x,
    const float4* __restrict__ wq,
    const float4* __restrict__ wp)
{
    int i = blockIdx.x * 256 + threadIdx.x;
    if (i >= ALL_F4) return;
    const float4* src;
    __half2* dst;
    int k;
    if (i < X_F4) {
        src = x;  dst = (__half2*)g_xh;    k = i;
    } else if (i < X_F4 + WQ_F4) {
        src = wq; dst = (__half2*)g_wqkvh; k = i - X_F4;
    } else {
        src = wp; dst = (__half2*)g_wph;   k = i - X_F4 - WQ_F4;
    }
    float4 v = src[k];
    dst[2 * k]     = __floats2half2_rn(v.x, v.y);
    dst[2 * k + 1] = __floats2half2_rn(v.z, v.w);
}

// ---------------------------------------------------------------------------
// fp16 tensor-core flash attention: QB=128, 3-stage KV ring, 3 CTAs/SM,
// fp16x2 softmax exp (P exponentiated pairwise on MUFU; ph IS the PV A-frag).
// ---------------------------------------------------------------------------
#define ATT_SMEM (16384 + 3 * 16384)   // 65536

__global__ __launch_bounds__(128, 3) void attn_h_kernel()
{
    extern __shared__ char smraw[];
    uint32_t smemB = smem_to_u32(smraw);

    int qb = gridDim.x - 1 - blockIdx.x;       // heavy blocks first
    int bh = blockIdx.y;
    int b = bh >> 4, h = bh & 15;
    int tid = threadIdx.x, lane = tid & 31, warp = tid >> 5;
    int tg = lane >> 2, ti = lane & 3;
    int t_ = lane >> 3, rr = lane & 7;
    int q0 = qb * 128;
    int kmax = 2 * qb + 1;

    int ldr  = tid >> 3;               // 0..15
    int lseg = tid & 7;
    uint32_t lsw = ((uint32_t)(lseg ^ (ldr & 7))) << 4;

    // Q tile (128 rows x 128B), committed with load_kv(0)
    #pragma unroll
    for (int u = 0; u < 8; u++) {
        int row = ldr + 16 * u;
        const __half* src = g_qkvh + (size_t)(b * Tsz + q0 + row) * 3072 + h * 64 + lseg * 8;
        CP_ASYNC16(smemB + (uint32_t)(row * 128) + lsw, src);
    }

    auto load_kv = [&](int kb) {
        if (kb <= kmax) {
            uint32_t kB = smemB + 16384 + (uint32_t)(kb % 3) * 16384;
            #pragma unroll
            for (int u = 0; u < 4; u++) {
                int row = ldr + 16 * u;
                size_t g = (size_t)(b * Tsz + kb * 64 + row) * 3072 + h * 64 + lseg * 8;
                CP_ASYNC16(kB + (uint32_t)(row * 128) + lsw, g_qkvh + g + 1024);
                CP_ASYNC16(kB + 8192 + (uint32_t)(row * 128) + lsw, g_qkvh + g + 2048);
            }
        }
        CP_COMMIT();
    };

    load_kv(0);   // Q rides in this group
    load_kv(1);

    uint32_t qrow[2], krow[4];
    #pragma unroll
    for (int i = 0; i < 2; i++)
        qrow[i] = (uint32_t)((warp * 32 + i * 16 + (t_ & 1) * 8 + rr) * 128);
    #pragma unroll
    for (int p = 0; p < 4; p++)
        krow[p] = (uint32_t)((p * 16 + (t_ >> 1) * 8 + rr) * 128);

    float o[2][8][4];
    #pragma unroll
    for (int i = 0; i < 2; i++)
        #pragma unroll
        for (int j = 0; j < 8; j++)
            #pragma unroll
            for (int q = 0; q < 4; q++) o[i][j][q] = 0.f;
    float mrow[2][2] = {{-1e30f, -1e30f}, {-1e30f, -1e30f}};
    float lsum[2][2] = {{0.f, 0.f}, {0.f, 0.f}};

    #pragma unroll 1
    for (int kb = 0; kb <= kmax; kb++) {
        CP_WAIT(1);
        __syncthreads();
        load_kv(kb + 2);

        uint32_t KsB = smemB + 16384 + (uint32_t)(kb % 3) * 16384;
        uint32_t VsB = KsB + 8192;

        // ---- S = Q K^T ----
        float s[2][8][4];
        #pragma unroll
        for (int i = 0; i < 2; i++)
            #pragma unroll
            for (int j = 0; j < 8; j++)
                #pragma unroll
                for (int q = 0; q < 4; q++) s[i][j][q] = 0.f;

        #pragma unroll
        for (int kt = 0; kt < 4; kt++) {
            uint32_t af[2][4], bk[4][4];
            ldsm4(smemB + qrow[0] + ((uint32_t)((kt * 2 + (t_ >> 1)) ^ rr) << 4), af[0]);
            ldsm4(smemB + qrow[1] + ((uint32_t)((kt * 2 + (t_ >> 1)) ^ rr) << 4), af[1]);
            #pragma unroll
            for (int p = 0; p < 4; p++)
                ldsm4(KsB + krow[p] + ((uint32_t)((kt * 2 + (t_ & 1)) ^ rr) << 4), bk[p]);
            #pragma unroll
            for (int i = 0; i < 2; i++)
                #pragma unroll
                for (int p = 0; p < 4; p++) {
                    MMA_F16(s[i][2 * p],     af[i], &bk[p][0]);
                    MMA_F16(s[i][2 * p + 1], af[i], &bk[p][2]);
                }
        }

        // ---- causal mask ----
        if (kb >= 2 * qb) {
            #pragma unroll
            for (int i = 0; i < 2; i++) {
                int row0 = q0 + warp * 32 + i * 16 + tg;
                #pragma unroll
                for (int j = 0; j < 8; j++) {
                    int col = kb * 64 + j * 8 + 2 * ti;
                    if (col     > row0    ) s[i][j][0] = -1e30f;
                    if (col + 1 > row0    ) s[i][j][1] = -1e30f;
                    if (col     > row0 + 8) s[i][j][2] = -1e30f;
                    if (col + 1 > row0 + 8) s[i][j][3] = -1e30f;
                }
            }
        }

        // ---- online softmax: exp2 in fp16x2 (P pairs born as A-fragments) ----
        uint32_t ph[2][8][2];
        float sc[2][2];
        #pragma unroll
        for (int i = 0; i < 2; i++) {
            float mt0 = -1e30f, mt1 = -1e30f;
            #pragma unroll
            for (int j = 0; j < 8; j++) {
                mt0 = fmaxf(mt0, fmaxf(s[i][j][0], s[i][j][1]));
                mt1 = fmaxf(mt1, fmaxf(s[i][j][2], s[i][j][3]));
            }
            mt0 = fmaxf(mt0, __shfl_xor_sync(0xffffffffu, mt0, 1));
            mt0 = fmaxf(mt0, __shfl_xor_sync(0xffffffffu, mt0, 2));
            mt1 = fmaxf(mt1, __shfl_xor_sync(0xffffffffu, mt1, 1));
            mt1 = fmaxf(mt1, __shfl_xor_sync(0xffffffffu, mt1, 2));

            float mn0 = fmaxf(mrow[i][0], mt0), mn1 = fmaxf(mrow[i][1], mt1);
            sc[i][0] = ex2(mrow[i][0] - mn0); sc[i][1] = ex2(mrow[i][1] - mn1);
            float ps0 = 0.f, ps1 = 0.f;
            #pragma unroll
            for (int j = 0; j < 8; j++) {
                uint32_t p01 = ex2h2(packh2(s[i][j][0] - mn0, s[i][j][1] - mn0));
                uint32_t p23 = ex2h2(packh2(s[i][j][2] - mn1, s[i][j][3] - mn1));
                ph[i][j][0] = p01;
                ph[i][j][1] = p23;
                float2 f0 = h2f2(p01);
                float2 f1 = h2f2(p23);
                ps0 += f0.x + f0.y;
                ps1 += f1.x + f1.y;
            }
            ps0 += __shfl_xor_sync(0xffffffffu, ps0, 1);
            ps0 += __shfl_xor_sync(0xffffffffu, ps0, 2);
            ps1 += __shfl_xor_sync(0xffffffffu, ps1, 1);
            ps1 += __shfl_xor_sync(0xffffffffu, ps1, 2);
            lsum[i][0] = lsum[i][0] * sc[i][0] + ps0; mrow[i][0] = mn0;
            lsum[i][1] = lsum[i][1] * sc[i][1] + ps1; mrow[i][1] = mn1;

            #pragma unroll
            for (int j = 0; j < 8; j++) {
                o[i][j][0] *= sc[i][0]; o[i][j][1] *= sc[i][0];
                o[i][j][2] *= sc[i][1]; o[i][j][3] *= sc[i][1];
            }
        }

        // ---- O += P V (ph already in A-fragment layout; V via ldsm.trans) ----
        #pragma unroll
        for (int kt = 0; kt < 4; kt++) {
            uint32_t bv[4][4], af[2][4];
            #pragma unroll
            for (int p = 0; p < 4; p++)
                ldsm4t(VsB + (uint32_t)((kt * 16 + (t_ & 1) * 8 + rr) * 128)
                           + ((uint32_t)((p * 2 + (t_ >> 1)) ^ rr) << 4), bv[p]);
            #pragma unroll
            for (int i = 0; i < 2; i++) {
                af[i][0] = ph[i][2 * kt][0];
                af[i][1] = ph[i][2 * kt][1];
                af[i][2] = ph[i][2 * kt + 1][0];
                af[i][3] = ph[i][2 * kt + 1][1];
            }
            #pragma unroll
            for (int i = 0; i < 2; i++)
                #pragma unroll
                for (int p = 0; p < 4; p++) {
                    MMA_F16(o[i][2 * p],     af[i], &bv[p][0]);
                    MMA_F16(o[i][2 * p + 1], af[i], &bv[p][2]);
                }
        }
    }

    // ---- epilogue: normalize, fp16, store y ----
    #pragma unroll
    for (int i = 0; i < 2; i++) {
        float i0 = 1.f / lsum[i][0], i1 = 1.f / lsum[i][1];
        size_t m0 = (size_t)(b * Tsz + q0 + warp * 32 + i * 16 + tg);
        #pragma unroll
        for (int jd = 0; jd < 8; jd++) {
            int col = h * 64 + jd * 8 + 2 * ti;
            *(uint32_t*)&g_yh[m0 * 1024 + col] =
                packh2(o[i][jd][0] * i0, o[i][jd][1] * i0);
            *(uint32_t*)&g_yh[(m0 + 8) * 1024 + col] =
                packh2(o[i][jd][2] * i1, o[i][jd][3] * i1);
        }
    }
}

// ---------------------------------------------------------------------------
extern "C" void kernel_launch(void* const* d_in, const int* in_sizes, int n_in,
                              void* d_out, int out_size)
{
    const float* x      = (const float*)d_in[0];
    const float* w_qkv  = (const float*)d_in[1];
    const float* b_qkv  = (const float*)d_in[2];
    const float* w_proj = (const float*)d_in[3];
    const float* b_proj = (const float*)d_in[4];
    float* out = (float*)d_out;

    __half* xh;    cudaGetSymbolAddress((void**)&xh,    g_xh);
    __half* wqkvh; cudaGetSymbolAddress((void**)&wqkvh, g_wqkvh);
    __half* wph;   cudaGetSymbolAddress((void**)&wph,   g_wph);
    __half* yh;    cudaGetSymbolAddress((void**)&yh,    g_yh);

    // 0) fused prep: fp16-convert x + both weights (natural layout, 1 launch)
    prep_kernel<<<(ALL_F4 + 255) / 256, 256>>>(
        (const float4*)x, (const float4*)w_qkv, (const float4*)w_proj);

    // 1) qkv = x @ w_qkv + b_qkv  -> g_qkvh fp16 (q pre-scaled)
    {
        cudaFuncSetAttribute(gemm_h_kernel,
                             cudaFuncAttributeMaxDynamicSharedMemorySize, GEMM_SMEM);
        dim3 grid(3 * Csz / 128, Mrows / 128);
        gemm_h_kernel<<<grid, 128, GEMM_SMEM>>>(xh, wqkvh, b_qkv, nullptr, 3 * Csz, 1);
    }

    // 2) fp16 flash attention -> g_yh
    {
        cudaFuncSetAttribute(attn_h_kernel,
                             cudaFuncAttributeMaxDynamicSharedMemorySize, ATT_SMEM);
        dim3 grid(Tsz / 128, Bsz * Hn);
        attn_h_kernel<<<grid, 128, ATT_SMEM>>>();
    }

    // 3) out = y @ w_proj + b_proj  (f32 output)
    {
        dim3 grid(Csz / 128, Mrows / 128);
        gemm_h_kernel<<<grid, 128, GEMM_SMEM>>>(yh, wph, b_proj, out, Csz, 0);
    }
}

// round 15
// speedup vs baseline: 1.5209x; 1.5209x over previous
#include <cuda_runtime.h>
#include <cuda_fp16.h>
#include <cstdint>
#include <cstddef>

#define Bsz   4
#define Tsz   2048
#define Csz   1024
#define Hn    16
#define Mrows (Bsz * Tsz)   // 8192

// 0.125 * log2(e): folded into q so softmax runs in exp2 domain
#define QSCALE 0.18033688011112042f

// Scratch (fp16 operands everywhere; f32 accumulation in-kernel)
__device__ __half g_qkvh [(size_t)Mrows * 3 * Csz];  // [8192, 3072]
__device__ __half g_yh   [(size_t)Mrows * Csz];      // [8192, 1024]
__device__ __half g_xh   [(size_t)Mrows * Csz];      // x in fp16
__device__ __half g_wqkvh[(size_t)Csz * 3 * Csz];    // [1024, 3072] natural
__device__ __half g_wph  [(size_t)Csz * Csz];        // [1024, 1024] natural

// ---------------------------------------------------------------------------
// Helpers (non-'a' PTX: cp.async + mma.sync + ldmatrix, sm_80 baseline)
// ---------------------------------------------------------------------------
__device__ __forceinline__ uint32_t smem_to_u32(const void* p) {
    uint32_t a;
    asm("{ .reg .u64 t; cvta.to.shared.u64 t, %1; cvt.u32.u64 %0, t; }"
        : "=r"(a) : "l"(p));
    return a;
}
__device__ __forceinline__ float ex2(float x) {
    float r;
    asm("ex2.approx.f32 %0, %1;" : "=f"(r) : "f"(x));
    return r;
}
__device__ __forceinline__ uint32_t ex2h2(uint32_t x) {
    uint32_t r;
    asm("ex2.approx.f16x2 %0, %1;" : "=r"(r) : "r"(x));
    return r;
}
__device__ __forceinline__ uint32_t packh2(float lo, float hi) {
    __half2 h = __floats2half2_rn(lo, hi);
    return *reinterpret_cast<uint32_t*>(&h);
}
__device__ __forceinline__ float2 h2f2(uint32_t p) {
    return __half22float2(*reinterpret_cast<__half2*>(&p));
}
__device__ __forceinline__ void ldsm4(uint32_t addr, uint32_t* r) {
    asm volatile("ldmatrix.sync.aligned.m8n8.x4.shared.b16 {%0,%1,%2,%3}, [%4];"
        : "=r"(r[0]), "=r"(r[1]), "=r"(r[2]), "=r"(r[3]) : "r"(addr));
}
__device__ __forceinline__ void ldsm4t(uint32_t addr, uint32_t* r) {
    asm volatile("ldmatrix.sync.aligned.m8n8.x4.trans.shared.b16 {%0,%1,%2,%3}, [%4];"
        : "=r"(r[0]), "=r"(r[1]), "=r"(r[2]), "=r"(r[3]) : "r"(addr));
}

#define CP_ASYNC16(dst, src) \
    asm volatile("cp.async.cg.shared.global [%0], [%1], 16;" :: "r"(dst), "l"(src) : "memory")
#define CP_COMMIT() asm volatile("cp.async.commit_group;" ::: "memory")
#define CP_WAIT(n)  asm volatile("cp.async.wait_group %0;" :: "n"(n) : "memory")

// D += A*B, m16n8k16 fp16 inputs, f32 accumulate (A row-major, B col-major)
#define MMA_F16(d, a, b) \
    asm volatile("mma.sync.aligned.m16n8k16.row.col.f32.f16.f16.f32 " \
        "{%0,%1,%2,%3}, {%4,%5,%6,%7}, {%8,%9}, {%0,%1,%2,%3};" \
        : "+f"((d)[0]), "+f"((d)[1]), "+f"((d)[2]), "+f"((d)[3]) \
        : "r"((a)[0]), "r"((a)[1]), "r"((a)[2]), "r"((a)[3]), \
          "r"((b)[0]), "r"((b)[1]))

// ---------------------------------------------------------------------------
// fp16 GEMM: C[M,N] = A[M,1024] @ W[1024,N] + bias   (W NATURAL layout)
// 128x128 CTA tile, BK=64, 3-stage cp.async, 128 threads (2x2 warps,
// warp tile 64x64). W tile [64k][128n] rows 256B via ldsm4t.
// qkvMode=1: fp16 out to g_qkvh (q pre-scaled).
// ---------------------------------------------------------------------------
#define KCH 16
#define STAGE_B 32768
#define GEMM_SMEM (3 * STAGE_B)

__global__ __launch_bounds__(128, 2) void gemm_h_kernel(
    const __half* __restrict__ A,
    const __half* __restrict__ W,
    const float* __restrict__ bias,
    float* __restrict__ Cf,
    int Ntot,
    int qkvMode)
{
    extern __shared__ char smraw[];
    uint32_t smemB = smem_to_u32(smraw);

    int tid = threadIdx.x, lane = tid & 31, warp = tid >> 5;
    int wm = warp >> 1, wn = warp & 1;
    int tg = lane >> 2, ti = lane & 3;
    int t_ = lane >> 3, rr = lane & 7;
    int row0 = blockIdx.y * 128, col0 = blockIdx.x * 128;

    int ldrA  = tid >> 3;
    int lsegA = tid & 7;
    uint32_t lswA = ((uint32_t)(lsegA ^ (ldrA & 7))) << 4;
    const __half* gA = A + (size_t)(row0 + ldrA) * 1024 + lsegA * 8;

    int ldrW  = tid >> 4;
    int lsegW = tid & 15;
    uint32_t lswW = ((uint32_t)(lsegW ^ ldrW)) << 4;
    const __half* gW = W + (size_t)ldrW * Ntot + col0 + lsegW * 8;

    uint32_t arow[4];
    #pragma unroll
    for (int i = 0; i < 4; i++)
        arow[i] = (uint32_t)((wm * 64 + i * 16 + (t_ & 1) * 8 + rr) * 128);

    float acc[4][8][4];
    #pragma unroll
    for (int i = 0; i < 4; i++)
        #pragma unroll
        for (int j = 0; j < 8; j++)
            #pragma unroll
            for (int q = 0; q < 4; q++) acc[i][j][q] = 0.f;

    auto load_stage = [&](int c) {
        if (c < KCH) {
            uint32_t base = smemB + (uint32_t)(c % 3) * STAGE_B;
            #pragma unroll
            for (int j = 0; j < 8; j++) {
                CP_ASYNC16(base + (uint32_t)((ldrA + 16 * j) * 128) + lswA,
                           gA + c * 64 + (size_t)j * 16 * 1024);
                CP_ASYNC16(base + 16384 + (uint32_t)((ldrW + 8 * j) * 256) + lswW,
                           gW + (size_t)(c * 64 + 8 * j) * Ntot);
            }
        }
        CP_COMMIT();
    };

    load_stage(0);
    load_stage(1);

    #pragma unroll 1
    for (int c = 0; c < KCH; ++c) {
        CP_WAIT(1);
        __syncthreads();
        load_stage(c + 2);

        uint32_t AsB = smemB + (uint32_t)(c % 3) * STAGE_B;
        uint32_t BsB = AsB + 16384;

        #pragma unroll
        for (int ks = 0; ks < 4; ks++) {
            uint32_t af[4][4], bf[4][4];
            #pragma unroll
            for (int i = 0; i < 4; i++)
                ldsm4(AsB + arow[i] + ((uint32_t)((ks * 2 + (t_ >> 1)) ^ rr) << 4), af[i]);
            #pragma unroll
            for (int p = 0; p < 4; p++)
                ldsm4t(BsB + (uint32_t)((ks * 16 + (t_ & 1) * 8 + rr) * 256)
                           + ((uint32_t)((wn * 8 + p * 2 + (t_ >> 1)) ^ rr) << 4), bf[p]);
            #pragma unroll
            for (int i = 0; i < 4; i++)
                #pragma unroll
                for (int p = 0; p < 4; p++) {
                    MMA_F16(acc[i][2 * p],     af[i], &bf[p][0]);
                    MMA_F16(acc[i][2 * p + 1], af[i], &bf[p][2]);
                }
        }
    }

    if (qkvMode) {
        float osc = (col0 < 1024) ? QSCALE : 1.0f;
        #pragma unroll
        for (int i = 0; i < 4; i++) {
            int m = row0 + wm * 64 + i * 16 + tg;
            #pragma unroll
            for (int j = 0; j < 8; j++) {
                int n = col0 + wn * 64 + j * 8 + 2 * ti;
                float bx = __ldg(bias + n), by = __ldg(bias + n + 1);
                uint32_t h0 = packh2((acc[i][j][0] + bx) * osc, (acc[i][j][1] + by) * osc);
                uint32_t h1 = packh2((acc[i][j][2] + bx) * osc, (acc[i][j][3] + by) * osc);
                *(uint32_t*)&g_qkvh[(size_t)m * 3072 + n] = h0;
                *(uint32_t*)&g_qkvh[(size_t)(m + 8) * 3072 + n] = h1;
            }
        }
    } else {
        #pragma unroll
        for (int i = 0; i < 4; i++) {
            int m = row0 + wm * 64 + i * 16 + tg;
            #pragma unroll
            for (int j = 0; j < 8; j++) {
                int n = col0 + wn * 64 + j * 8 + 2 * ti;
                float bx = __ldg(bias + n), by = __ldg(bias + n + 1);
                *(float2*)&Cf[(size_t)m * Ntot + n] =
                    make_float2(acc[i][j][0] + bx, acc[i][j][1] + by);
                *(float2*)&Cf[(size_t)(m + 8) * Ntot + n] =
                    make_float2(acc[i][j][2] + bx, acc[i][j][3] + by);
            }
        }
    }
}

// ---------------------------------------------------------------------------
// Fused prep: f32 -> fp16 for x, w_qkv, w_proj in ONE launch (no transposes).
// ---------------------------------------------------------------------------
#define X_F4   (Mrows * Csz / 4)
#define WQ_F4  (Csz * 3 * Csz / 4)
#define WP_F4  (Csz * Csz / 4)
#define ALL_F4 (X_F4 + WQ_F4 + WP_F4)

__global__ __launch_bounds__(256) void prep_kernel(
    const float4* __restrict__ x,
    const float4* __restrict__ wq,
    const float4* __restrict__ wp)
{
    int i = blockIdx.x * 256 + threadIdx.x;
    if (i >= ALL_F4) return;
    const float4* src;
    __half2* dst;
    int k;
    if (i < X_F4) {
        src = x;  dst = (__half2*)g_xh;    k = i;
    } else if (i < X_F4 + WQ_F4) {
        src = wq; dst = (__half2*)g_wqkvh; k = i - X_F4;
    } else {
        src = wp; dst = (__half2*)g_wph;   k = i - X_F4 - WQ_F4;
    }
    float4 v = src[k];
    dst[2 * k]     = __floats2half2_rn(v.x, v.y);
    dst[2 * k + 1] = __floats2half2_rn(v.z, v.w);
}

// ---------------------------------------------------------------------------
// fp16 tensor-core flash attention: QB=128, 3-stage KV ring, 2 CTAs/SM
// (R13 occupancy), fp16x2 softmax exp (ph IS the PV A-fragment).
// ---------------------------------------------------------------------------
#define ATT_SMEM (16384 + 3 * 16384)   // 65536

__global__ __launch_bounds__(128, 2) void attn_h_kernel()
{
    extern __shared__ char smraw[];
    uint32_t smemB = smem_to_u32(smraw);

    int qb = gridDim.x - 1 - blockIdx.x;       // heavy blocks first
    int bh = blockIdx.y;
    int b = bh >> 4, h = bh & 15;
    int tid = threadIdx.x, lane = tid & 31, warp = tid >> 5;
    int tg = lane >> 2, ti = lane & 3;
    int t_ = lane >> 3, rr = lane & 7;
    int q0 = qb * 128;
    int kmax = 2 * qb + 1;

    int ldr  = tid >> 3;               // 0..15
    int lseg = tid & 7;
    uint32_t lsw = ((uint32_t)(lseg ^ (ldr & 7))) << 4;

    // Q tile (128 rows x 128B), committed with load_kv(0)
    #pragma unroll
    for (int u = 0; u < 8; u++) {
        int row = ldr + 16 * u;
        const __half* src = g_qkvh + (size_t)(b * Tsz + q0 + row) * 3072 + h * 64 + lseg * 8;
        CP_ASYNC16(smemB + (uint32_t)(row * 128) + lsw, src);
    }

    auto load_kv = [&](int kb) {
        if (kb <= kmax) {
            uint32_t kB = smemB + 16384 + (uint32_t)(kb % 3) * 16384;
            #pragma unroll
            for (int u = 0; u < 4; u++) {
                int row = ldr + 16 * u;
                size_t g = (size_t)(b * Tsz + kb * 64 + row) * 3072 + h * 64 + lseg * 8;
                CP_ASYNC16(kB + (uint32_t)(row * 128) + lsw, g_qkvh + g + 1024);
                CP_ASYNC16(kB + 8192 + (uint32_t)(row * 128) + lsw, g_qkvh + g + 2048);
            }
        }
        CP_COMMIT();
    };

    load_kv(0);   // Q rides in this group
    load_kv(1);

    uint32_t qrow[2], krow[4];
    #pragma unroll
    for (int i = 0; i < 2; i++)
        qrow[i] = (uint32_t)((warp * 32 + i * 16 + (t_ & 1) * 8 + rr) * 128);
    #pragma unroll
    for (int p = 0; p < 4; p++)
        krow[p] = (uint32_t)((p * 16 + (t_ >> 1) * 8 + rr) * 128);

    float o[2][8][4];
    #pragma unroll
    for (int i = 0; i < 2; i++)
        #pragma unroll
        for (int j = 0; j < 8; j++)
            #pragma unroll
            for (int q = 0; q < 4; q++) o[i][j][q] = 0.f;
    float mrow[2][2] = {{-1e30f, -1e30f}, {-1e30f, -1e30f}};
    float lsum[2][2] = {{0.f, 0.f}, {0.f, 0.f}};

    #pragma unroll 1
    for (int kb = 0; kb <= kmax; kb++) {
        CP_WAIT(1);
        __syncthreads();
        load_kv(kb + 2);

        uint32_t KsB = smemB + 16384 + (uint32_t)(kb % 3) * 16384;
        uint32_t VsB = KsB + 8192;

        // ---- S = Q K^T ----
        float s[2][8][4];
        #pragma unroll
        for (int i = 0; i < 2; i++)
            #pragma unroll
            for (int j = 0; j < 8; j++)
                #pragma unroll
                for (int q = 0; q < 4; q++) s[i][j][q] = 0.f;

        #pragma unroll
        for (int kt = 0; kt < 4; kt++) {
            uint32_t af[2][4], bk[4][4];
            ldsm4(smemB + qrow[0] + ((uint32_t)((kt * 2 + (t_ >> 1)) ^ rr) << 4), af[0]);
            ldsm4(smemB + qrow[1] + ((uint32_t)((kt * 2 + (t_ >> 1)) ^ rr) << 4), af[1]);
            #pragma unroll
            for (int p = 0; p < 4; p++)
                ldsm4(KsB + krow[p] + ((uint32_t)((kt * 2 + (t_ & 1)) ^ rr) << 4), bk[p]);
            #pragma unroll
            for (int i = 0; i < 2; i++)
                #pragma unroll
                for (int p = 0; p < 4; p++) {
                    MMA_F16(s[i][2 * p],     af[i], &bk[p][0]);
                    MMA_F16(s[i][2 * p + 1], af[i], &bk[p][2]);
                }
        }

        // ---- causal mask ----
        if (kb >= 2 * qb) {
            #pragma unroll
            for (int i = 0; i < 2; i++) {
                int row0 = q0 + warp * 32 + i * 16 + tg;
                #pragma unroll
                for (int j = 0; j < 8; j++) {
                    int col = kb * 64 + j * 8 + 2 * ti;
                    if (col     > row0    ) s[i][j][0] = -1e30f;
                    if (col + 1 > row0    ) s[i][j][1] = -1e30f;
                    if (col     > row0 + 8) s[i][j][2] = -1e30f;
                    if (col + 1 > row0 + 8) s[i][j][3] = -1e30f;
                }
            }
        }

        // ---- online softmax: exp2 in fp16x2 (P pairs born as A-fragments) ----
        uint32_t ph[2][8][2];
        float sc[2][2];
        #pragma unroll
        for (int i = 0; i < 2; i++) {
            float mt0 = -1e30f, mt1 = -1e30f;
            #pragma unroll
            for (int j = 0; j < 8; j++) {
                mt0 = fmaxf(mt0, fmaxf(s[i][j][0], s[i][j][1]));
                mt1 = fmaxf(mt1, fmaxf(s[i][j][2], s[i][j][3]));
            }
            mt0 = fmaxf(mt0, __shfl_xor_sync(0xffffffffu, mt0, 1));
            mt0 = fmaxf(mt0, __shfl_xor_sync(0xffffffffu, mt0, 2));
            mt1 = fmaxf(mt1, __shfl_xor_sync(0xffffffffu, mt1, 1));
            mt1 = fmaxf(mt1, __shfl_xor_sync(0xffffffffu, mt1, 2));

            float mn0 = fmaxf(mrow[i][0], mt0), mn1 = fmaxf(mrow[i][1], mt1);
            sc[i][0] = ex2(mrow[i][0] - mn0); sc[i][1] = ex2(mrow[i][1] - mn1);
            float ps0 = 0.f, ps1 = 0.f;
            #pragma unroll
            for (int j = 0; j < 8; j++) {
                uint32_t p01 = ex2h2(packh2(s[i][j][0] - mn0, s[i][j][1] - mn0));
                uint32_t p23 = ex2h2(packh2(s[i][j][2] - mn1, s[i][j][3] - mn1));
                ph[i][j][0] = p01;
                ph[i][j][1] = p23;
                float2 f0 = h2f2(p01);
                float2 f1 = h2f2(p23);
                ps0 += f0.x + f0.y;
                ps1 += f1.x + f1.y;
            }
            ps0 += __shfl_xor_sync(0xffffffffu, ps0, 1);
            ps0 += __shfl_xor_sync(0xffffffffu, ps0, 2);
            ps1 += __shfl_xor_sync(0xffffffffu, ps1, 1);
            ps1 += __shfl_xor_sync(0xffffffffu, ps1, 2);
            lsum[i][0] = lsum[i][0] * sc[i][0] + ps0; mrow[i][0] = mn0;
            lsum[i][1] = lsum[i][1] * sc[i][1] + ps1; mrow[i][1] = mn1;

            #pragma unroll
            for (int j = 0; j < 8; j++) {
                o[i][j][0] *= sc[i][0]; o[i][j][1] *= sc[i][0];
                o[i][j][2] *= sc[i][1]; o[i][j][3] *= sc[i][1];
            }
        }

        // ---- O += P V (ph already in A-fragment layout; V via ldsm.trans) ----
        #pragma unroll
        for (int kt = 0; kt < 4; kt++) {
            uint32_t bv[4][4], af[2][4];
            #pragma unroll
            for (int p = 0; p < 4; p++)
                ldsm4t(VsB + (uint32_t)((kt * 16 + (t_ & 1) * 8 + rr) * 128)
                           + ((uint32_t)((p * 2 + (t_ >> 1)) ^ rr) << 4), bv[p]);
            #pragma unroll
            for (int i = 0; i < 2; i++) {
                af[i][0] = ph[i][2 * kt][0];
                af[i][1] = ph[i][2 * kt][1];
                af[i][2] = ph[i][2 * kt + 1][0];
                af[i][3] = ph[i][2 * kt + 1][1];
            }
            #pragma unroll
            for (int i = 0; i < 2; i++)
                #pragma unroll
                for (int p = 0; p < 4; p++) {
                    MMA_F16(o[i][2 * p],     af[i], &bv[p][0]);
                    MMA_F16(o[i][2 * p + 1], af[i], &bv[p][2]);
                }
        }
    }

    // ---- epilogue: normalize, fp16, store y ----
    #pragma unroll
    for (int i = 0; i < 2; i++) {
        float i0 = 1.f / lsum[i][0], i1 = 1.f / lsum[i][1];
        size_t m0 = (size_t)(b * Tsz + q0 + warp * 32 + i * 16 + tg);
        #pragma unroll
        for (int jd = 0; jd < 8; jd++) {
            int col = h * 64 + jd * 8 + 2 * ti;
            *(uint32_t*)&g_yh[m0 * 1024 + col] =
                packh2(o[i][jd][0] * i0, o[i][jd][1] * i0);
            *(uint32_t*)&g_yh[(m0 + 8) * 1024 + col] =
                packh2(o[i][jd][2] * i1, o[i][jd][3] * i1);
        }
    }
}

// ---------------------------------------------------------------------------
extern "C" void kernel_launch(void* const* d_in, const int* in_sizes, int n_in,
                              void* d_out, int out_size)
{
    const float* x      = (const float*)d_in[0];
    const float* w_qkv  = (const float*)d_in[1];
    const float* b_qkv  = (const float*)d_in[2];
    const float* w_proj = (const float*)d_in[3];
    const float* b_proj = (const float*)d_in[4];
    float* out = (float*)d_out;

    __half* xh;    cudaGetSymbolAddress((void**)&xh,    g_xh);
    __half* wqkvh; cudaGetSymbolAddress((void**)&wqkvh, g_wqkvh);
    __half* wph;   cudaGetSymbolAddress((void**)&wph,   g_wph);
    __half* yh;    cudaGetSymbolAddress((void**)&yh,    g_yh);

    // 0) fused prep: fp16-convert x + both weights (natural layout, 1 launch)
    prep_kernel<<<(ALL_F4 + 255) / 256, 256>>>(
        (const float4*)x, (const float4*)w_qkv, (const float4*)w_proj);

    // 1) qkv = x @ w_qkv + b_qkv  -> g_qkvh fp16 (q pre-scaled)
    {
        cudaFuncSetAttribute(gemm_h_kernel,
                             cudaFuncAttributeMaxDynamicSharedMemorySize, GEMM_SMEM);
        dim3 grid(3 * Csz / 128, Mrows / 128);
        gemm_h_kernel<<<grid, 128, GEMM_SMEM>>>(xh, wqkvh, b_qkv, nullptr, 3 * Csz, 1);
    }

    // 2) fp16 flash attention -> g_yh
    {
        cudaFuncSetAttribute(attn_h_kernel,
                             cudaFuncAttributeMaxDynamicSharedMemorySize, ATT_SMEM);
        dim3 grid(Tsz / 128, Bsz * Hn);
        attn_h_kernel<<<grid, 128, ATT_SMEM>>>();
    }

    // 3) out = y @ w_proj + b_proj  (f32 output)
    {
        dim3 grid(Csz / 128, Mrows / 128);
        gemm_h_kernel<<<grid, 128, GEMM_SMEM>>>(yh, wph, b_proj, out, Csz, 0);
    }
}

// round 16
// speedup vs baseline: 1.5393x; 1.0121x over previous
#include <cuda_runtime.h>
#include <cuda_fp16.h>
#include <cstdint>
#include <cstddef>

#define Bsz   4
#define Tsz   2048
#define Csz   1024
#define Hn    16
#define Mrows (Bsz * Tsz)   // 8192

// 0.125 * log2(e): folded into q so softmax runs in exp2 domain
#define QSCALE 0.18033688011112042f

// Scratch (fp16 operands everywhere; f32 accumulation in-kernel)
__device__ __half g_qkvh [(size_t)Mrows * 3 * Csz];  // [8192, 3072]
__device__ __half g_yh   [(size_t)Mrows * Csz];      // [8192, 1024]
__device__ __half g_xh   [(size_t)Mrows * Csz];      // x in fp16
__device__ __half g_wqkvh[(size_t)Csz * 3 * Csz];    // [1024, 3072] natural
__device__ __half g_wph  [(size_t)Csz * Csz];        // [1024, 1024] natural

// ---------------------------------------------------------------------------
// Helpers (non-'a' PTX: cp.async + mma.sync + ldmatrix, sm_80 baseline)
// ---------------------------------------------------------------------------
__device__ __forceinline__ uint32_t smem_to_u32(const void* p) {
    uint32_t a;
    asm("{ .reg .u64 t; cvta.to.shared.u64 t, %1; cvt.u32.u64 %0, t; }"
        : "=r"(a) : "l"(p));
    return a;
}
__device__ __forceinline__ float ex2(float x) {
    float r;
    asm("ex2.approx.f32 %0, %1;" : "=f"(r) : "f"(x));
    return r;
}
__device__ __forceinline__ uint32_t ex2h2(uint32_t x) {
    uint32_t r;
    asm("ex2.approx.f16x2 %0, %1;" : "=r"(r) : "r"(x));
    return r;
}
__device__ __forceinline__ uint32_t packh2(float lo, float hi) {
    __half2 h = __floats2half2_rn(lo, hi);
    return *reinterpret_cast<uint32_t*>(&h);
}
__device__ __forceinline__ float2 h2f2(uint32_t p) {
    return __half22float2(*reinterpret_cast<__half2*>(&p));
}
__device__ __forceinline__ void ldsm4(uint32_t addr, uint32_t* r) {
    asm volatile("ldmatrix.sync.aligned.m8n8.x4.shared.b16 {%0,%1,%2,%3}, [%4];"
        : "=r"(r[0]), "=r"(r[1]), "=r"(r[2]), "=r"(r[3]) : "r"(addr));
}
__device__ __forceinline__ void ldsm4t(uint32_t addr, uint32_t* r) {
    asm volatile("ldmatrix.sync.aligned.m8n8.x4.trans.shared.b16 {%0,%1,%2,%3}, [%4];"
        : "=r"(r[0]), "=r"(r[1]), "=r"(r[2]), "=r"(r[3]) : "r"(addr));
}

#define CP_ASYNC16(dst, src) \
    asm volatile("cp.async.cg.shared.global [%0], [%1], 16;" :: "r"(dst), "l"(src) : "memory")
#define CP_COMMIT() asm volatile("cp.async.commit_group;" ::: "memory")
#define CP_WAIT(n)  asm volatile("cp.async.wait_group %0;" :: "n"(n) : "memory")

// D += A*B, m16n8k16 fp16 inputs, f32 accumulate (A row-major, B col-major)
#define MMA_F16(d, a, b) \
    asm volatile("mma.sync.aligned.m16n8k16.row.col.f32.f16.f16.f32 " \
        "{%0,%1,%2,%3}, {%4,%5,%6,%7}, {%8,%9}, {%0,%1,%2,%3};" \
        : "+f"((d)[0]), "+f"((d)[1]), "+f"((d)[2]), "+f"((d)[3]) \
        : "r"((a)[0]), "r"((a)[1]), "r"((a)[2]), "r"((a)[3]), \
          "r"((b)[0]), "r"((b)[1]))

// ---------------------------------------------------------------------------
// fp16 GEMM: C[M,N] = A[M,1024] @ W[1024,N] + bias   (W NATURAL layout)
// 128x128 CTA tile, BK=64, 3-stage cp.async, 128 threads (2x2 warps,
// warp tile 64x64). W tile [64k][128n] rows 256B via ldsm4t.
// qkvMode=1: fp16 out to g_qkvh (q pre-scaled).
// ---------------------------------------------------------------------------
#define KCH 16
#define STAGE_B 32768
#define GEMM_SMEM (3 * STAGE_B)

__global__ __launch_bounds__(128, 2) void gemm_h_kernel(
    const __half* __restrict__ A,
    const __half* __restrict__ W,
    const float* __restrict__ bias,
    float* __restrict__ Cf,
    int Ntot,
    int qkvMode)
{
    extern __shared__ char smraw[];
    uint32_t smemB = smem_to_u32(smraw);

    int tid = threadIdx.x, lane = tid & 31, warp = tid >> 5;
    int wm = warp >> 1, wn = warp & 1;
    int tg = lane >> 2, ti = lane & 3;
    int t_ = lane >> 3, rr = lane & 7;
    int row0 = blockIdx.y * 128, col0 = blockIdx.x * 128;

    int ldrA  = tid >> 3;
    int lsegA = tid & 7;
    uint32_t lswA = ((uint32_t)(lsegA ^ (ldrA & 7))) << 4;
    const __half* gA = A + (size_t)(row0 + ldrA) * 1024 + lsegA * 8;

    int ldrW  = tid >> 4;
    int lsegW = tid & 15;
    uint32_t lswW = ((uint32_t)(lsegW ^ ldrW)) << 4;
    const __half* gW = W + (size_t)ldrW * Ntot + col0 + lsegW * 8;

    uint32_t arow[4];
    #pragma unroll
    for (int i = 0; i < 4; i++)
        arow[i] = (uint32_t)((wm * 64 + i * 16 + (t_ & 1) * 8 + rr) * 128);

    float acc[4][8][4];
    #pragma unroll
    for (int i = 0; i < 4; i++)
        #pragma unroll
        for (int j = 0; j < 8; j++)
            #pragma unroll
            for (int q = 0; q < 4; q++) acc[i][j][q] = 0.f;

    auto load_stage = [&](int c) {
        if (c < KCH) {
            uint32_t base = smemB + (uint32_t)(c % 3) * STAGE_B;
            #pragma unroll
            for (int j = 0; j < 8; j++) {
                CP_ASYNC16(base + (uint32_t)((ldrA + 16 * j) * 128) + lswA,
                           gA + c * 64 + (size_t)j * 16 * 1024);
                CP_ASYNC16(base + 16384 + (uint32_t)((ldrW + 8 * j) * 256) + lswW,
                           gW + (size_t)(c * 64 + 8 * j) * Ntot);
            }
        }
        CP_COMMIT();
    };

    load_stage(0);
    load_stage(1);

    #pragma unroll 1
    for (int c = 0; c < KCH; ++c) {
        CP_WAIT(1);
        __syncthreads();
        load_stage(c + 2);

        uint32_t AsB = smemB + (uint32_t)(c % 3) * STAGE_B;
        uint32_t BsB = AsB + 16384;

        #pragma unroll
        for (int ks = 0; ks < 4; ks++) {
            uint32_t af[4][4], bf[4][4];
            #pragma unroll
            for (int i = 0; i < 4; i++)
                ldsm4(AsB + arow[i] + ((uint32_t)((ks * 2 + (t_ >> 1)) ^ rr) << 4), af[i]);
            #pragma unroll
            for (int p = 0; p < 4; p++)
                ldsm4t(BsB + (uint32_t)((ks * 16 + (t_ & 1) * 8 + rr) * 256)
                           + ((uint32_t)((wn * 8 + p * 2 + (t_ >> 1)) ^ rr) << 4), bf[p]);
            #pragma unroll
            for (int i = 0; i < 4; i++)
                #pragma unroll
                for (int p = 0; p < 4; p++) {
                    MMA_F16(acc[i][2 * p],     af[i], &bf[p][0]);
                    MMA_F16(acc[i][2 * p + 1], af[i], &bf[p][2]);
                }
        }
    }

    if (qkvMode) {
        float osc = (col0 < 1024) ? QSCALE : 1.0f;
        #pragma unroll
        for (int i = 0; i < 4; i++) {
            int m = row0 + wm * 64 + i * 16 + tg;
            #pragma unroll
            for (int j = 0; j < 8; j++) {
                int n = col0 + wn * 64 + j * 8 + 2 * ti;
                float bx = __ldg(bias + n), by = __ldg(bias + n + 1);
                uint32_t h0 = packh2((acc[i][j][0] + bx) * osc, (acc[i][j][1] + by) * osc);
                uint32_t h1 = packh2((acc[i][j][2] + bx) * osc, (acc[i][j][3] + by) * osc);
                *(uint32_t*)&g_qkvh[(size_t)m * 3072 + n] = h0;
                *(uint32_t*)&g_qkvh[(size_t)(m + 8) * 3072 + n] = h1;
            }
        }
    } else {
        #pragma unroll
        for (int i = 0; i < 4; i++) {
            int m = row0 + wm * 64 + i * 16 + tg;
            #pragma unroll
            for (int j = 0; j < 8; j++) {
                int n = col0 + wn * 64 + j * 8 + 2 * ti;
                float bx = __ldg(bias + n), by = __ldg(bias + n + 1);
                *(float2*)&Cf[(size_t)m * Ntot + n] =
                    make_float2(acc[i][j][0] + bx, acc[i][j][1] + by);
                *(float2*)&Cf[(size_t)(m + 8) * Ntot + n] =
                    make_float2(acc[i][j][2] + bx, acc[i][j][3] + by);
            }
        }
    }
}

// ---------------------------------------------------------------------------
// Fused prep: f32 -> fp16 for x, w_qkv, w_proj in ONE launch (no transposes).
// ---------------------------------------------------------------------------
#define X_F4   (Mrows * Csz / 4)
#define WQ_F4  (Csz * 3 * Csz / 4)
#define WP_F4  (Csz * Csz / 4)
#define ALL_F4 (X_F4 + WQ_F4 + WP_F4)

__global__ __launch_bounds__(256) void prep_kernel(
    const float4* __restrict__ x,
    const float4* __restrict__ wq,
    const float4* __restrict__ wp)
{
    int i = blockIdx.x * 256 + threadIdx.x;
    if (i >= ALL_F4) return;
    const float4* src;
    __half2* dst;
    int k;
    if (i < X_F4) {
        src = x;  dst = (__half2*)g_xh;    k = i;
    } else if (i < X_F4 + WQ_F4) {
        src = wq; dst = (__half2*)g_wqkvh; k = i - X_F4;
    } else {
        src = wp; dst = (__half2*)g_wph;   k = i - X_F4 - WQ_F4;
    }
    float4 v = src[k];
    dst[2 * k]     = __floats2half2_rn(v.x, v.y);
    dst[2 * k + 1] = __floats2half2_rn(v.z, v.w);
}

// ---------------------------------------------------------------------------
// fp16 tensor-core flash attention: QB=128, 3-stage KV ring, 2 CTAs/SM,
// fp16x2 softmax exp, Q FRAGMENTS HOISTED into registers (loop-invariant;
// kills 16KB/block of crossbar traffic).
// ---------------------------------------------------------------------------
#define ATT_SMEM (16384 + 3 * 16384)   // 65536

__global__ __launch_bounds__(128, 2) void attn_h_kernel()
{
    extern __shared__ char smraw[];
    uint32_t smemB = smem_to_u32(smraw);

    int qb = gridDim.x - 1 - blockIdx.x;       // heavy blocks first
    int bh = blockIdx.y;
    int b = bh >> 4, h = bh & 15;
    int tid = threadIdx.x, lane = tid & 31, warp = tid >> 5;
    int tg = lane >> 2, ti = lane & 3;
    int t_ = lane >> 3, rr = lane & 7;
    int q0 = qb * 128;
    int kmax = 2 * qb + 1;

    int ldr  = tid >> 3;               // 0..15
    int lseg = tid & 7;
    uint32_t lsw = ((uint32_t)(lseg ^ (ldr & 7))) << 4;

    // Q tile (128 rows x 128B), committed with load_kv(0)
    #pragma unroll
    for (int u = 0; u < 8; u++) {
        int row = ldr + 16 * u;
        const __half* src = g_qkvh + (size_t)(b * Tsz + q0 + row) * 3072 + h * 64 + lseg * 8;
        CP_ASYNC16(smemB + (uint32_t)(row * 128) + lsw, src);
    }

    auto load_kv = [&](int kb) {
        if (kb <= kmax) {
            uint32_t kB = smemB + 16384 + (uint32_t)(kb % 3) * 16384;
            #pragma unroll
            for (int u = 0; u < 4; u++) {
                int row = ldr + 16 * u;
                size_t g = (size_t)(b * Tsz + kb * 64 + row) * 3072 + h * 64 + lseg * 8;
                CP_ASYNC16(kB + (uint32_t)(row * 128) + lsw, g_qkvh + g + 1024);
                CP_ASYNC16(kB + 8192 + (uint32_t)(row * 128) + lsw, g_qkvh + g + 2048);
            }
        }
        CP_COMMIT();
    };

    load_kv(0);   // Q rides in this group
    load_kv(1);

    uint32_t qrow[2], krow[4];
    #pragma unroll
    for (int i = 0; i < 2; i++)
        qrow[i] = (uint32_t)((warp * 32 + i * 16 + (t_ & 1) * 8 + rr) * 128);
    #pragma unroll
    for (int p = 0; p < 4; p++)
        krow[p] = (uint32_t)((p * 16 + (t_ >> 1) * 8 + rr) * 128);

    // ---- hoist: group0 (Q + KV0) ready; read Q fragments ONCE ----
    CP_WAIT(1);
    __syncthreads();
    uint32_t qf[4][2][4];          // [kt][i][frag]
    #pragma unroll
    for (int kt = 0; kt < 4; kt++) {
        ldsm4(smemB + qrow[0] + ((uint32_t)((kt * 2 + (t_ >> 1)) ^ rr) << 4), qf[kt][0]);
        ldsm4(smemB + qrow[1] + ((uint32_t)((kt * 2 + (t_ >> 1)) ^ rr) << 4), qf[kt][1]);
    }

    float o[2][8][4];
    #pragma unroll
    for (int i = 0; i < 2; i++)
        #pragma unroll
        for (int j = 0; j < 8; j++)
            #pragma unroll
            for (int q = 0; q < 4; q++) o[i][j][q] = 0.f;
    float mrow[2][2] = {{-1e30f, -1e30f}, {-1e30f, -1e30f}};
    float lsum[2][2] = {{0.f, 0.f}, {0.f, 0.f}};

    #pragma unroll 1
    for (int kb = 0; kb <= kmax; kb++) {
        if (kb > 0) {
            CP_WAIT(1);
            __syncthreads();
        }
        load_kv(kb + 2);

        uint32_t KsB = smemB + 16384 + (uint32_t)(kb % 3) * 16384;
        uint32_t VsB = KsB + 8192;

        // ---- S = Q K^T (Q frags from registers) ----
        float s[2][8][4];
        #pragma unroll
        for (int i = 0; i < 2; i++)
            #pragma unroll
            for (int j = 0; j < 8; j++)
                #pragma unroll
                for (int q = 0; q < 4; q++) s[i][j][q] = 0.f;

        #pragma unroll
        for (int kt = 0; kt < 4; kt++) {
            uint32_t bk[4][4];
            #pragma unroll
            for (int p = 0; p < 4; p++)
                ldsm4(KsB + krow[p] + ((uint32_t)((kt * 2 + (t_ & 1)) ^ rr) << 4), bk[p]);
            #pragma unroll
            for (int i = 0; i < 2; i++)
                #pragma unroll
                for (int p = 0; p < 4; p++) {
                    MMA_F16(s[i][2 * p],     qf[kt][i], &bk[p][0]);
                    MMA_F16(s[i][2 * p + 1], qf[kt][i], &bk[p][2]);
                }
        }

        // ---- causal mask ----
        if (kb >= 2 * qb) {
            #pragma unroll
            for (int i = 0; i < 2; i++) {
                int row0 = q0 + warp * 32 + i * 16 + tg;
                #pragma unroll
                for (int j = 0; j < 8; j++) {
                    int col = kb * 64 + j * 8 + 2 * ti;
                    if (col     > row0    ) s[i][j][0] = -1e30f;
                    if (col + 1 > row0    ) s[i][j][1] = -1e30f;
                    if (col     > row0 + 8) s[i][j][2] = -1e30f;
                    if (col + 1 > row0 + 8) s[i][j][3] = -1e30f;
                }
            }
        }

        // ---- online softmax: exp2 in fp16x2 (P pairs born as A-fragments) ----
        uint32_t ph[2][8][2];
        float sc[2][2];
        #pragma unroll
        for (int i = 0; i < 2; i++) {
            float mt0 = -1e30f, mt1 = -1e30f;
            #pragma unroll
            for (int j = 0; j < 8; j++) {
                mt0 = fmaxf(mt0, fmaxf(s[i][j][0], s[i][j][1]));
                mt1 = fmaxf(mt1, fmaxf(s[i][j][2], s[i][j][3]));
            }
            mt0 = fmaxf(mt0, __shfl_xor_sync(0xffffffffu, mt0, 1));
            mt0 = fmaxf(mt0, __shfl_xor_sync(0xffffffffu, mt0, 2));
            mt1 = fmaxf(mt1, __shfl_xor_sync(0xffffffffu, mt1, 1));
            mt1 = fmaxf(mt1, __shfl_xor_sync(0xffffffffu, mt1, 2));

            float mn0 = fmaxf(mrow[i][0], mt0), mn1 = fmaxf(mrow[i][1], mt1);
            sc[i][0] = ex2(mrow[i][0] - mn0); sc[i][1] = ex2(mrow[i][1] - mn1);
            float ps0 = 0.f, ps1 = 0.f;
            #pragma unroll
            for (int j = 0; j < 8; j++) {
                uint32_t p01 = ex2h2(packh2(s[i][j][0] - mn0, s[i][j][1] - mn0));
                uint32_t p23 = ex2h2(packh2(s[i][j][2] - mn1, s[i][j][3] - mn1));
                ph[i][j][0] = p01;
                ph[i][j][1] = p23;
                float2 f0 = h2f2(p01);
                float2 f1 = h2f2(p23);
                ps0 += f0.x + f0.y;
                ps1 += f1.x + f1.y;
            }
            ps0 += __shfl_xor_sync(0xffffffffu, ps0, 1);
            ps0 += __shfl_xor_sync(0xffffffffu, ps0, 2);
            ps1 += __shfl_xor_sync(0xffffffffu, ps1, 1);
            ps1 += __shfl_xor_sync(0xffffffffu, ps1, 2);
            lsum[i][0] = lsum[i][0] * sc[i][0] + ps0; mrow[i][0] = mn0;
            lsum[i][1] = lsum[i][1] * sc[i][1] + ps1; mrow[i][1] = mn1;

            #pragma unroll
            for (int j = 0; j < 8; j++) {
                o[i][j][0] *= sc[i][0]; o[i][j][1] *= sc[i][0];
                o[i][j][2] *= sc[i][1]; o[i][j][3] *= sc[i][1];
            }
        }

        // ---- O += P V (ph already in A-fragment layout; V via ldsm.trans) ----
        #pragma unroll
        for (int kt = 0; kt < 4; kt++) {
            uint32_t bv[4][4], af[2][4];
            #pragma unroll
            for (int p = 0; p < 4; p++)
                ldsm4t(VsB + (uint32_t)((kt * 16 + (t_ & 1) * 8 + rr) * 128)
                           + ((uint32_t)((p * 2 + (t_ >> 1)) ^ rr) << 4), bv[p]);
            #pragma unroll
            for (int i = 0; i < 2; i++) {
                af[i][0] = ph[i][2 * kt][0];
                af[i][1] = ph[i][2 * kt][1];
                af[i][2] = ph[i][2 * kt + 1][0];
                af[i][3] = ph[i][2 * kt + 1][1];
            }
            #pragma unroll
            for (int i = 0; i < 2; i++)
                #pragma unroll
                for (int p = 0; p < 4; p++) {
                    MMA_F16(o[i][2 * p],     af[i], &bv[p][0]);
                    MMA_F16(o[i][2 * p + 1], af[i], &bv[p][2]);
                }
        }
    }

    // ---- epilogue: normalize, fp16, store y ----
    #pragma unroll
    for (int i = 0; i < 2; i++) {
        float i0 = 1.f / lsum[i][0], i1 = 1.f / lsum[i][1];
        size_t m0 = (size_t)(b * Tsz + q0 + warp * 32 + i * 16 + tg);
        #pragma unroll
        for (int jd = 0; jd < 8; jd++) {
            int col = h * 64 + jd * 8 + 2 * ti;
            *(uint32_t*)&g_yh[m0 * 1024 + col] =
                packh2(o[i][jd][0] * i0, o[i][jd][1] * i0);
            *(uint32_t*)&g_yh[(m0 + 8) * 1024 + col] =
                packh2(o[i][jd][2] * i1, o[i][jd][3] * i1);
        }
    }
}

// ---------------------------------------------------------------------------
extern "C" void kernel_launch(void* const* d_in, const int* in_sizes, int n_in,
                              void* d_out, int out_size)
{
    const float* x      = (const float*)d_in[0];
    const float* w_qkv  = (const float*)d_in[1];
    const float* b_qkv  = (const float*)d_in[2];
    const float* w_proj = (const float*)d_in[3];
    const float* b_proj = (const float*)d_in[4];
    float* out = (float*)d_out;

    __half* xh;    cudaGetSymbolAddress((void**)&xh,    g_xh);
    __half* wqkvh; cudaGetSymbolAddress((void**)&wqkvh, g_wqkvh);
    __half* wph;   cudaGetSymbolAddress((void**)&wph,   g_wph);
    __half* yh;    cudaGetSymbolAddress((void**)&yh,    g_yh);

    // 0) fused prep: fp16-convert x + both weights (natural layout, 1 launch)
    prep_kernel<<<(ALL_F4 + 255) / 256, 256>>>(
        (const float4*)x, (const float4*)w_qkv, (const float4*)w_proj);

    // 1) qkv = x @ w_qkv + b_qkv  -> g_qkvh fp16 (q pre-scaled)
    {
        cudaFuncSetAttribute(gemm_h_kernel,
                             cudaFuncAttributeMaxDynamicSharedMemorySize, GEMM_SMEM);
        dim3 grid(3 * Csz / 128, Mrows / 128);
        gemm_h_kernel<<<grid, 128, GEMM_SMEM>>>(xh, wqkvh, b_qkv, nullptr, 3 * Csz, 1);
    }

    // 2) fp16 flash attention -> g_yh
    {
        cudaFuncSetAttribute(attn_h_kernel,
                             cudaFuncAttributeMaxDynamicSharedMemorySize, ATT_SMEM);
        dim3 grid(Tsz / 128, Bsz * Hn);
        attn_h_kernel<<<grid, 128, ATT_SMEM>>>();
    }

    // 3) out = y @ w_proj + b_proj  (f32 output)
    {
        dim3 grid(Csz / 128, Mrows / 128);
        gemm_h_kernel<<<grid, 128, GEMM_SMEM>>>(yh, wph, b_proj, out, Csz, 0);
    }
}

// round 17
// speedup vs baseline: 1.5404x; 1.0007x over previous
#include <cuda_runtime.h>
#include <cuda_fp16.h>
#include <cstdint>
#include <cstddef>

#define Bsz   4
#define Tsz   2048
#define Csz   1024
#define Hn    16
#define Mrows (Bsz * Tsz)   // 8192

// 0.125 * log2(e): folded into q so softmax runs in exp2 domain
#define QSCALE 0.18033688011112042f

// Scratch (fp16 operands everywhere; f32 accumulation in-kernel)
__device__ __half g_qkvh [(size_t)Mrows * 3 * Csz];  // [8192, 3072]
__device__ __half g_yh   [(size_t)Mrows * Csz];      // [8192, 1024]
__device__ __half g_xh   [(size_t)Mrows * Csz];      // x in fp16
__device__ __half g_wqkvh[(size_t)Csz * 3 * Csz];    // [1024, 3072] natural
__device__ __half g_wph  [(size_t)Csz * Csz];        // [1024, 1024] natural

// ---------------------------------------------------------------------------
// Helpers (non-'a' PTX: cp.async + mma.sync + ldmatrix, sm_80 baseline)
// ---------------------------------------------------------------------------
__device__ __forceinline__ uint32_t smem_to_u32(const void* p) {
    uint32_t a;
    asm("{ .reg .u64 t; cvta.to.shared.u64 t, %1; cvt.u32.u64 %0, t; }"
        : "=r"(a) : "l"(p));
    return a;
}
__device__ __forceinline__ float ex2(float x) {
    float r;
    asm("ex2.approx.f32 %0, %1;" : "=f"(r) : "f"(x));
    return r;
}
__device__ __forceinline__ uint32_t ex2h2(uint32_t x) {
    uint32_t r;
    asm("ex2.approx.f16x2 %0, %1;" : "=r"(r) : "r"(x));
    return r;
}
__device__ __forceinline__ uint32_t packh2(float lo, float hi) {
    __half2 h = __floats2half2_rn(lo, hi);
    return *reinterpret_cast<uint32_t*>(&h);
}
__device__ __forceinline__ float2 h2f2(uint32_t p) {
    return __half22float2(*reinterpret_cast<__half2*>(&p));
}
__device__ __forceinline__ void ldsm4(uint32_t addr, uint32_t* r) {
    asm volatile("ldmatrix.sync.aligned.m8n8.x4.shared.b16 {%0,%1,%2,%3}, [%4];"
        : "=r"(r[0]), "=r"(r[1]), "=r"(r[2]), "=r"(r[3]) : "r"(addr));
}
__device__ __forceinline__ void ldsm4t(uint32_t addr, uint32_t* r) {
    asm volatile("ldmatrix.sync.aligned.m8n8.x4.trans.shared.b16 {%0,%1,%2,%3}, [%4];"
        : "=r"(r[0]), "=r"(r[1]), "=r"(r[2]), "=r"(r[3]) : "r"(addr));
}

#define CP_ASYNC16(dst, src) \
    asm volatile("cp.async.cg.shared.global [%0], [%1], 16;" :: "r"(dst), "l"(src) : "memory")
#define CP_COMMIT() asm volatile("cp.async.commit_group;" ::: "memory")
#define CP_WAIT(n)  asm volatile("cp.async.wait_group %0;" :: "n"(n) : "memory")

// D += A*B, m16n8k16 fp16 inputs, f32 accumulate (A row-major, B col-major)
#define MMA_F16(d, a, b) \
    asm volatile("mma.sync.aligned.m16n8k16.row.col.f32.f16.f16.f32 " \
        "{%0,%1,%2,%3}, {%4,%5,%6,%7}, {%8,%9}, {%0,%1,%2,%3};" \
        : "+f"((d)[0]), "+f"((d)[1]), "+f"((d)[2]), "+f"((d)[3]) \
        : "r"((a)[0]), "r"((a)[1]), "r"((a)[2]), "r"((a)[3]), \
          "r"((b)[0]), "r"((b)[1]))

// ---------------------------------------------------------------------------
// fp16 GEMM: C[M,N] = A[M,1024] @ W[1024,N] + bias   (W NATURAL layout)
// 128x128 CTA tile, BK=64, 3-stage cp.async, 128 threads (2x2 warps,
// warp tile 64x64). W tile [64k][128n] rows 256B via ldsm4t.
// qkvMode=1: fp16 out to g_qkvh (q pre-scaled).
// ---------------------------------------------------------------------------
#define KCH 16
#define STAGE_B 32768
#define GEMM_SMEM (3 * STAGE_B)

__global__ __launch_bounds__(128, 2) void gemm_h_kernel(
    const __half* __restrict__ A,
    const __half* __restrict__ W,
    const float* __restrict__ bias,
    float* __restrict__ Cf,
    int Ntot,
    int qkvMode)
{
    extern __shared__ char smraw[];
    uint32_t smemB = smem_to_u32(smraw);

    int tid = threadIdx.x, lane = tid & 31, warp = tid >> 5;
    int wm = warp >> 1, wn = warp & 1;
    int tg = lane >> 2, ti = lane & 3;
    int t_ = lane >> 3, rr = lane & 7;
    int row0 = blockIdx.y * 128, col0 = blockIdx.x * 128;

    int ldrA  = tid >> 3;
    int lsegA = tid & 7;
    uint32_t lswA = ((uint32_t)(lsegA ^ (ldrA & 7))) << 4;
    const __half* gA = A + (size_t)(row0 + ldrA) * 1024 + lsegA * 8;

    int ldrW  = tid >> 4;
    int lsegW = tid & 15;
    uint32_t lswW = ((uint32_t)(lsegW ^ ldrW)) << 4;
    const __half* gW = W + (size_t)ldrW * Ntot + col0 + lsegW * 8;

    uint32_t arow[4];
    #pragma unroll
    for (int i = 0; i < 4; i++)
        arow[i] = (uint32_t)((wm * 64 + i * 16 + (t_ & 1) * 8 + rr) * 128);

    float acc[4][8][4];
    #pragma unroll
    for (int i = 0; i < 4; i++)
        #pragma unroll
        for (int j = 0; j < 8; j++)
            #pragma unroll
            for (int q = 0; q < 4; q++) acc[i][j][q] = 0.f;

    auto load_stage = [&](int c) {
        if (c < KCH) {
            uint32_t base = smemB + (uint32_t)(c % 3) * STAGE_B;
            #pragma unroll
            for (int j = 0; j < 8; j++) {
                CP_ASYNC16(base + (uint32_t)((ldrA + 16 * j) * 128) + lswA,
                           gA + c * 64 + (size_t)j * 16 * 1024);
                CP_ASYNC16(base + 16384 + (uint32_t)((ldrW + 8 * j) * 256) + lswW,
                           gW + (size_t)(c * 64 + 8 * j) * Ntot);
            }
        }
        CP_COMMIT();
    };

    load_stage(0);
    load_stage(1);

    #pragma unroll 1
    for (int c = 0; c < KCH; ++c) {
        CP_WAIT(1);
        __syncthreads();
        load_stage(c + 2);

        uint32_t AsB = smemB + (uint32_t)(c % 3) * STAGE_B;
        uint32_t BsB = AsB + 16384;

        #pragma unroll
        for (int ks = 0; ks < 4; ks++) {
            uint32_t af[4][4], bf[4][4];
            #pragma unroll
            for (int i = 0; i < 4; i++)
                ldsm4(AsB + arow[i] + ((uint32_t)((ks * 2 + (t_ >> 1)) ^ rr) << 4), af[i]);
            #pragma unroll
            for (int p = 0; p < 4; p++)
                ldsm4t(BsB + (uint32_t)((ks * 16 + (t_ & 1) * 8 + rr) * 256)
                           + ((uint32_t)((wn * 8 + p * 2 + (t_ >> 1)) ^ rr) << 4), bf[p]);
            #pragma unroll
            for (int i = 0; i < 4; i++)
                #pragma unroll
                for (int p = 0; p < 4; p++) {
                    MMA_F16(acc[i][2 * p],     af[i], &bf[p][0]);
                    MMA_F16(acc[i][2 * p + 1], af[i], &bf[p][2]);
                }
        }
    }

    if (qkvMode) {
        float osc = (col0 < 1024) ? QSCALE : 1.0f;
        #pragma unroll
        for (int i = 0; i < 4; i++) {
            int m = row0 + wm * 64 + i * 16 + tg;
            #pragma unroll
            for (int j = 0; j < 8; j++) {
                int n = col0 + wn * 64 + j * 8 + 2 * ti;
                float bx = __ldg(bias + n), by = __ldg(bias + n + 1);
                uint32_t h0 = packh2((acc[i][j][0] + bx) * osc, (acc[i][j][1] + by) * osc);
                uint32_t h1 = packh2((acc[i][j][2] + bx) * osc, (acc[i][j][3] + by) * osc);
                *(uint32_t*)&g_qkvh[(size_t)m * 3072 + n] = h0;
                *(uint32_t*)&g_qkvh[(size_t)(m + 8) * 3072 + n] = h1;
            }
        }
    } else {
        #pragma unroll
        for (int i = 0; i < 4; i++) {
            int m = row0 + wm * 64 + i * 16 + tg;
            #pragma unroll
            for (int j = 0; j < 8; j++) {
                int n = col0 + wn * 64 + j * 8 + 2 * ti;
                float bx = __ldg(bias + n), by = __ldg(bias + n + 1);
                *(float2*)&Cf[(size_t)m * Ntot + n] =
                    make_float2(acc[i][j][0] + bx, acc[i][j][1] + by);
                *(float2*)&Cf[(size_t)(m + 8) * Ntot + n] =
                    make_float2(acc[i][j][2] + bx, acc[i][j][3] + by);
            }
        }
    }
}

// ---------------------------------------------------------------------------
// Fused prep: f32 -> fp16 for x, w_qkv, w_proj in ONE launch (no transposes).
// ---------------------------------------------------------------------------
#define X_F4   (Mrows * Csz / 4)
#define WQ_F4  (Csz * 3 * Csz / 4)
#define WP_F4  (Csz * Csz / 4)
#define ALL_F4 (X_F4 + WQ_F4 + WP_F4)

__global__ __launch_bounds__(256) void prep_kernel(
    const float4* __restrict__ x,
    const float4* __restrict__ wq,
    const float4* __restrict__ wp)
{
    int i = blockIdx.x * 256 + threadIdx.x;
    if (i >= ALL_F4) return;
    const float4* src;
    __half2* dst;
    int k;
    if (i < X_F4) {
        src = x;  dst = (__half2*)g_xh;    k = i;
    } else if (i < X_F4 + WQ_F4) {
        src = wq; dst = (__half2*)g_wqkvh; k = i - X_F4;
    } else {
        src = wp; dst = (__half2*)g_wph;   k = i - X_F4 - WQ_F4;
    }
    float4 v = src[k];
    dst[2 * k]     = __floats2half2_rn(v.x, v.y);
    dst[2 * k + 1] = __floats2half2_rn(v.z, v.w);
}

// ---------------------------------------------------------------------------
// fp16 tensor-core flash attention: QB=128, 2 CTAs/SM, fp16x2 softmax exp,
// Q frags hoisted. 128-KEY pipeline stages (two 64-key sub-blocks per
// barrier): 3-stage ring of 32KB stages = Q 16KB + 96KB = 112KB.
// Barrier count per CTA halves vs 64-key stages.
// ---------------------------------------------------------------------------
#define ATT_SMEM (16384 + 3 * 32768)   // 114688

__global__ __launch_bounds__(128, 2) void attn_h_kernel()
{
    extern __shared__ char smraw[];
    uint32_t smemB = smem_to_u32(smraw);

    int qb = gridDim.x - 1 - blockIdx.x;       // heavy blocks first
    int bh = blockIdx.y;
    int b = bh >> 4, h = bh & 15;
    int tid = threadIdx.x, lane = tid & 31, warp = tid >> 5;
    int tg = lane >> 2, ti = lane & 3;
    int t_ = lane >> 3, rr = lane & 7;
    int q0 = qb * 128;

    int ldr  = tid >> 3;               // 0..15
    int lseg = tid & 7;
    uint32_t lsw = ((uint32_t)(lseg ^ (ldr & 7))) << 4;

    // Q tile (128 rows x 128B), committed with load_kv(0)
    #pragma unroll
    for (int u = 0; u < 8; u++) {
        int row = ldr + 16 * u;
        const __half* src = g_qkvh + (size_t)(b * Tsz + q0 + row) * 3072 + h * 64 + lseg * 8;
        CP_ASYNC16(smemB + (uint32_t)(row * 128) + lsw, src);
    }

    // 128-key stage: [K 16KB][V 16KB], each two 64-row halves of 8KB
    auto load_kv = [&](int kb) {
        if (kb <= qb) {
            uint32_t kB = smemB + 16384 + (uint32_t)(kb % 3) * 32768;
            #pragma unroll
            for (int u = 0; u < 8; u++) {
                int row = ldr + 16 * u;     // 0..127
                size_t g = (size_t)(b * Tsz + kb * 128 + row) * 3072 + h * 64 + lseg * 8;
                CP_ASYNC16(kB + (uint32_t)(row * 128) + lsw, g_qkvh + g + 1024);
                CP_ASYNC16(kB + 16384 + (uint32_t)(row * 128) + lsw, g_qkvh + g + 2048);
            }
        }
        CP_COMMIT();
    };

    load_kv(0);   // Q rides in this group
    load_kv(1);

    uint32_t qrow[2], krow[4];
    #pragma unroll
    for (int i = 0; i < 2; i++)
        qrow[i] = (uint32_t)((warp * 32 + i * 16 + (t_ & 1) * 8 + rr) * 128);
    #pragma unroll
    for (int p = 0; p < 4; p++)
        krow[p] = (uint32_t)((p * 16 + (t_ >> 1) * 8 + rr) * 128);

    // ---- hoist: group0 (Q + KV0) ready; read Q fragments ONCE ----
    CP_WAIT(1);
    __syncthreads();
    uint32_t qf[4][2][4];          // [kt][i][frag]
    #pragma unroll
    for (int kt = 0; kt < 4; kt++) {
        ldsm4(smemB + qrow[0] + ((uint32_t)((kt * 2 + (t_ >> 1)) ^ rr) << 4), qf[kt][0]);
        ldsm4(smemB + qrow[1] + ((uint32_t)((kt * 2 + (t_ >> 1)) ^ rr) << 4), qf[kt][1]);
    }

    float o[2][8][4];
    #pragma unroll
    for (int i = 0; i < 2; i++)
        #pragma unroll
        for (int j = 0; j < 8; j++)
            #pragma unroll
            for (int q = 0; q < 4; q++) o[i][j][q] = 0.f;
    float mrow[2][2] = {{-1e30f, -1e30f}, {-1e30f, -1e30f}};
    float lsum[2][2] = {{0.f, 0.f}, {0.f, 0.f}};

    #pragma unroll 1
    for (int kb = 0; kb <= qb; kb++) {
        if (kb > 0) {
            CP_WAIT(1);
            __syncthreads();
        }
        load_kv(kb + 2);

        uint32_t stB = smemB + 16384 + (uint32_t)(kb % 3) * 32768;

        #pragma unroll 1
        for (int half = 0; half < 2; half++) {
            uint32_t KsB = stB + (uint32_t)half * 8192;
            uint32_t VsB = stB + 16384 + (uint32_t)half * 8192;

            // ---- S = Q K^T (Q frags from registers) ----
            float s[2][8][4];
            #pragma unroll
            for (int i = 0; i < 2; i++)
                #pragma unroll
                for (int j = 0; j < 8; j++)
                    #pragma unroll
                    for (int q = 0; q < 4; q++) s[i][j][q] = 0.f;

            #pragma unroll
            for (int kt = 0; kt < 4; kt++) {
                uint32_t bk[4][4];
                #pragma unroll
                for (int p = 0; p < 4; p++)
                    ldsm4(KsB + krow[p] + ((uint32_t)((kt * 2 + (t_ & 1)) ^ rr) << 4), bk[p]);
                #pragma unroll
                for (int i = 0; i < 2; i++)
                    #pragma unroll
                    for (int p = 0; p < 4; p++) {
                        MMA_F16(s[i][2 * p],     qf[kt][i], &bk[p][0]);
                        MMA_F16(s[i][2 * p + 1], qf[kt][i], &bk[p][2]);
                    }
            }

            // ---- causal mask (only the diagonal 128-key block) ----
            if (kb == qb) {
                int colb = (2 * kb + half) * 64;
                #pragma unroll
                for (int i = 0; i < 2; i++) {
                    int row0 = q0 + warp * 32 + i * 16 + tg;
                    #pragma unroll
                    for (int j = 0; j < 8; j++) {
                        int col = colb + j * 8 + 2 * ti;
                        if (col     > row0    ) s[i][j][0] = -1e30f;
                        if (col + 1 > row0    ) s[i][j][1] = -1e30f;
                        if (col     > row0 + 8) s[i][j][2] = -1e30f;
                        if (col + 1 > row0 + 8) s[i][j][3] = -1e30f;
                    }
                }
            }

            // ---- online softmax: exp2 in fp16x2 ----
            uint32_t ph[2][8][2];
            float sc[2][2];
            #pragma unroll
            for (int i = 0; i < 2; i++) {
                float mt0 = -1e30f, mt1 = -1e30f;
                #pragma unroll
                for (int j = 0; j < 8; j++) {
                    mt0 = fmaxf(mt0, fmaxf(s[i][j][0], s[i][j][1]));
                    mt1 = fmaxf(mt1, fmaxf(s[i][j][2], s[i][j][3]));
                }
                mt0 = fmaxf(mt0, __shfl_xor_sync(0xffffffffu, mt0, 1));
                mt0 = fmaxf(mt0, __shfl_xor_sync(0xffffffffu, mt0, 2));
                mt1 = fmaxf(mt1, __shfl_xor_sync(0xffffffffu, mt1, 1));
                mt1 = fmaxf(mt1, __shfl_xor_sync(0xffffffffu, mt1, 2));

                float mn0 = fmaxf(mrow[i][0], mt0), mn1 = fmaxf(mrow[i][1], mt1);
                sc[i][0] = ex2(mrow[i][0] - mn0); sc[i][1] = ex2(mrow[i][1] - mn1);
                float ps0 = 0.f, ps1 = 0.f;
                #pragma unroll
                for (int j = 0; j < 8; j++) {
                    uint32_t p01 = ex2h2(packh2(s[i][j][0] - mn0, s[i][j][1] - mn0));
                    uint32_t p23 = ex2h2(packh2(s[i][j][2] - mn1, s[i][j][3] - mn1));
                    ph[i][j][0] = p01;
                    ph[i][j][1] = p23;
                    float2 f0 = h2f2(p01);
                    float2 f1 = h2f2(p23);
                    ps0 += f0.x + f0.y;
                    ps1 += f1.x + f1.y;
                }
                ps0 += __shfl_xor_sync(0xffffffffu, ps0, 1);
                ps0 += __shfl_xor_sync(0xffffffffu, ps0, 2);
                ps1 += __shfl_xor_sync(0xffffffffu, ps1, 1);
                ps1 += __shfl_xor_sync(0xffffffffu, ps1, 2);
                lsum[i][0] = lsum[i][0] * sc[i][0] + ps0; mrow[i][0] = mn0;
                lsum[i][1] = lsum[i][1] * sc[i][1] + ps1; mrow[i][1] = mn1;

                #pragma unroll
                for (int j = 0; j < 8; j++) {
                    o[i][j][0] *= sc[i][0]; o[i][j][1] *= sc[i][0];
                    o[i][j][2] *= sc[i][1]; o[i][j][3] *= sc[i][1];
                }
            }

            // ---- O += P V ----
            #pragma unroll
            for (int kt = 0; kt < 4; kt++) {
                uint32_t bv[4][4], af[2][4];
                #pragma unroll
                for (int p = 0; p < 4; p++)
                    ldsm4t(VsB + (uint32_t)((kt * 16 + (t_ & 1) * 8 + rr) * 128)
                               + ((uint32_t)((p * 2 + (t_ >> 1)) ^ rr) << 4), bv[p]);
                #pragma unroll
                for (int i = 0; i < 2; i++) {
                    af[i][0] = ph[i][2 * kt][0];
                    af[i][1] = ph[i][2 * kt][1];
                    af[i][2] = ph[i][2 * kt + 1][0];
                    af[i][3] = ph[i][2 * kt + 1][1];
                }
                #pragma unroll
                for (int i = 0; i < 2; i++)
                    #pragma unroll
                    for (int p = 0; p < 4; p++) {
                        MMA_F16(o[i][2 * p],     af[i], &bv[p][0]);
                        MMA_F16(o[i][2 * p + 1], af[i], &bv[p][2]);
                    }
            }
        }
    }

    // ---- epilogue: normalize, fp16, store y ----
    #pragma unroll
    for (int i = 0; i < 2; i++) {
        float i0 = 1.f / lsum[i][0], i1 = 1.f / lsum[i][1];
        size_t m0 = (size_t)(b * Tsz + q0 + warp * 32 + i * 16 + tg);
        #pragma unroll
        for (int jd = 0; jd < 8; jd++) {
            int col = h * 64 + jd * 8 + 2 * ti;
            *(uint32_t*)&g_yh[m0 * 1024 + col] =
                packh2(o[i][jd][0] * i0, o[i][jd][1] * i0);
            *(uint32_t*)&g_yh[(m0 + 8) * 1024 + col] =
                packh2(o[i][jd][2] * i1, o[i][jd][3] * i1);
        }
    }
}

// ---------------------------------------------------------------------------
extern "C" void kernel_launch(void* const* d_in, const int* in_sizes, int n_in,
                              void* d_out, int out_size)
{
    const float* x      = (const float*)d_in[0];
    const float* w_qkv  = (const float*)d_in[1];
    const float* b_qkv  = (const float*)d_in[2];
    const float* w_proj = (const float*)d_in[3];
    const float* b_proj = (const float*)d_in[4];
    float* out = (float*)d_out;

    __half* xh;    cudaGetSymbolAddress((void**)&xh,    g_xh);
    __half* wqkvh; cudaGetSymbolAddress((void**)&wqkvh, g_wqkvh);
    __half* wph;   cudaGetSymbolAddress((void**)&wph,   g_wph);
    __half* yh;    cudaGetSymbolAddress((void**)&yh,    g_yh);

    // 0) fused prep: fp16-convert x + both weights (natural layout, 1 launch)
    prep_kernel<<<(ALL_F4 + 255) / 256, 256>>>(
        (const float4*)x, (const float4*)w_qkv, (const float4*)w_proj);

    // 1) qkv = x @ w_qkv + b_qkv  -> g_qkvh fp16 (q pre-scaled)
    {
        cudaFuncSetAttribute(gemm_h_kernel,
                             cudaFuncAttributeMaxDynamicSharedMemorySize, GEMM_SMEM);
        dim3 grid(3 * Csz / 128, Mrows / 128);
        gemm_h_kernel<<<grid, 128, GEMM_SMEM>>>(xh, wqkvh, b_qkv, nullptr, 3 * Csz, 1);
    }

    // 2) fp16 flash attention (128-key stages) -> g_yh
    {
        cudaFuncSetAttribute(attn_h_kernel,
                             cudaFuncAttributeMaxDynamicSharedMemorySize, ATT_SMEM);
        dim3 grid(Tsz / 128, Bsz * Hn);
        attn_h_kernel<<<grid, 128, ATT_SMEM>>>();
    }

    // 3) out = y @ w_proj + b_proj  (f32 output)
    {
        dim3 grid(Csz / 128, Mrows / 128);
        gemm_h_kernel<<<grid, 128, GEMM_SMEM>>>(yh, wph, b_proj, out, Csz, 0);
    }
}